// round 14
// baseline (speedup 1.0000x reference)
#include <cuda_runtime.h>
#include <cuda_bf16.h>
#include <cstdint>
#include <math.h>

#define NN 50000
#define EE 800000
#define NTILES (EE / 128)          // 6250 edge tiles
#define PERSIST_BLOCKS 296         // 148 SMs x 2 blocks

// ---------------- scratch (device globals; no allocations allowed) ----------
__device__ float g_y[NN * 64];      // messages y = h @ Wl^T
__device__ float g_r[NN * 64];      // root    r = h @ Wr^T
__device__ float g_h[NN * 64];      // pre-BN hidden
__device__ float g_stats[128];      // per-channel sum / sumsq
__device__ float g_ab[256];         // BN affine: [a1|c1|a2|c2]
__device__ float g_P[NN * 128];     // P = hf @ Wm1[:, :64]^T + bm1
__device__ float g_Q[NN * 128];     // Q = hf @ Wm1[:, 80:]^T
__device__ int   g_deg[NN];         // in-degree
__device__ int   g_off[NN + 1];     // CSR offsets
__device__ int   g_fill[NN];        // fill cursors
__device__ int   g_csr[EE];         // src node per CSR slot (grouped by dst)
__device__ int   g_eid[EE];         // original edge id per CSR slot
__device__ int   g_cdst[EE];        // dst node per CSR slot
__device__ int   g_idx64;           // 1 if edge_index is int64, 0 if int32

// ---------------- portable bf16 HMMA (sm_80+ PTX, works on compute_103) -----
__device__ __forceinline__ void mma16816(float* d,
                                         uint32_t a0, uint32_t a1,
                                         uint32_t a2, uint32_t a3,
                                         uint32_t b0, uint32_t b1) {
    asm volatile(
        "mma.sync.aligned.m16n8k16.row.col.f32.bf16.bf16.f32 "
        "{%0,%1,%2,%3}, {%4,%5,%6,%7}, {%8,%9}, {%0,%1,%2,%3};"
        : "+f"(d[0]), "+f"(d[1]), "+f"(d[2]), "+f"(d[3])
        : "r"(a0), "r"(a1), "r"(a2), "r"(a3), "r"(b0), "r"(b1));
}

__device__ __forceinline__ void ldsm_x4(uint32_t& r0, uint32_t& r1,
                                        uint32_t& r2, uint32_t& r3,
                                        uint32_t addr) {
    asm volatile(
        "ldmatrix.sync.aligned.m8n8.x4.shared.b16 {%0,%1,%2,%3}, [%4];"
        : "=r"(r0), "=r"(r1), "=r"(r2), "=r"(r3) : "r"(addr));
}

__device__ __forceinline__ uint32_t smem_u32(const void* p) {
    return (uint32_t)__cvta_generic_to_shared(p);
}

__device__ __forceinline__ void split_bf16x2(float2 v, uint32_t& h, uint32_t& l) {
    __nv_bfloat16 h0 = __float2bfloat16_rn(v.x);
    __nv_bfloat16 h1 = __float2bfloat16_rn(v.y);
    __nv_bfloat16 l0 = __float2bfloat16_rn(v.x - __bfloat162float(h0));
    __nv_bfloat16 l1 = __float2bfloat16_rn(v.y - __bfloat162float(h1));
    h = ((uint32_t)__bfloat16_as_ushort(h1) << 16) | __bfloat16_as_ushort(h0);
    l = ((uint32_t)__bfloat16_as_ushort(l1) << 16) | __bfloat16_as_ushort(l0);
}

__device__ __forceinline__ void split_bf16x4(float4 v, uint2& hp, uint2& lp) {
    split_bf16x2(make_float2(v.x, v.y), hp.x, lp.x);
    split_bf16x2(make_float2(v.z, v.w), hp.y, lp.y);
}

// ---------------- init: zero deg/fill/stats + dtype detection ----------------
__global__ void init_kernel(const void* ei, int* __restrict__ deg,
                            int* __restrict__ fill, float* __restrict__ stats) {
    int i = blockIdx.x * blockDim.x + threadIdx.x;
    if (i < NN) { deg[i] = 0; fill[i] = 0; }
    if (i < 128) stats[i] = 0.f;
    if (i == 0) {
        const unsigned int* w = (const unsigned int*)ei;
        int f = 1;
        for (int k = 0; k < 32; k++)
            if (w[2 * k + 1] != 0u) f = 0;   // int32 data: odd words random
        g_idx64 = f;
    }
}

__device__ __forceinline__ int load_idx(const void* ei, long long i, int is64) {
    if (is64) return (int)__ldg(((const long long*)ei) + i);
    return __ldg(((const int*)ei) + i);
}

// ---------------- CSR build --------------------------------------------------
__global__ void hist_kernel(const void* __restrict__ ei, int* __restrict__ deg) {
    int e = blockIdx.x * blockDim.x + threadIdx.x;
    if (e >= EE) return;
    int dst = load_idx(ei, (long long)EE + e, g_idx64);
    atomicAdd(deg + dst, 1);
}

__global__ void scan_kernel(const int* __restrict__ deg, int* __restrict__ off) {
    __shared__ int part[1024];
    int tid = threadIdx.x;                 // 1024 threads, 1 block
    const int CH = (NN + 1023) / 1024;     // 49
    int s0 = tid * CH;
    int lsum = 0;
    for (int i = 0; i < CH; i++) {
        int idx = s0 + i;
        if (idx < NN) lsum += deg[idx];
    }
    part[tid] = lsum;
    __syncthreads();
    for (int d = 1; d < 1024; d <<= 1) {
        int v = (tid >= d) ? part[tid - d] : 0;
        __syncthreads();
        part[tid] += v;
        __syncthreads();
    }
    int run = (tid == 0) ? 0 : part[tid - 1];
    for (int i = 0; i < CH; i++) {
        int idx = s0 + i;
        if (idx < NN) { off[idx] = run; run += deg[idx]; }
    }
    if (tid == 1023) off[NN] = run;
}

__global__ void csr_fill_kernel(const void* __restrict__ ei,
                                const int* __restrict__ off,
                                int* __restrict__ fill,
                                int* __restrict__ csr,
                                int* __restrict__ eid,
                                int* __restrict__ cdst) {
    int e = blockIdx.x * blockDim.x + threadIdx.x;
    if (e >= EE) return;
    int is64 = g_idx64;
    int src = load_idx(ei, e, is64);
    int dst = load_idx(ei, (long long)EE + e, is64);
    int slot = off[dst] + atomicAdd(fill + dst, 1);
    csr[slot] = src;
    eid[slot] = e;
    cdst[slot] = dst;
}

// ---------------- aggregate + finalize + BN stats (half-warp float4) ---------
__global__ void aggregate_kernel(const int* __restrict__ off,
                                 const int* __restrict__ csr,
                                 const float* __restrict__ y,
                                 const float* __restrict__ r,
                                 const float* __restrict__ bl,
                                 float* __restrict__ h,
                                 float* __restrict__ stats) {
    __shared__ float sbuf[128];
    int tid = threadIdx.x;
    int lane = tid & 31, wid = tid >> 5;
    if (tid < 128) sbuf[tid] = 0.f;
    __syncthreads();

    int n = blockIdx.x * 8 + wid;          // 8 warps = 8 nodes per block
    int beg = off[n], end = off[n + 1];
    int half = lane >> 4;                  // 0 or 1
    int c4 = (lane & 15) * 4;              // channel base
    float4 a0 = make_float4(0.f, 0.f, 0.f, 0.f);
    float4 a1 = make_float4(0.f, 0.f, 0.f, 0.f);
    float4 a2 = make_float4(0.f, 0.f, 0.f, 0.f);
    float4 a3 = make_float4(0.f, 0.f, 0.f, 0.f);

    for (int base = beg; base < end; base += 32) {
        int idx = base + lane;
        int s = (idx < end) ? __ldg(csr + idx) : 0;
        int m = min(32, end - base);
        int j = 0;
        for (; j + 8 <= m; j += 8) {
            int s0 = __shfl_sync(0xffffffffu, s, j + half);
            int s1 = __shfl_sync(0xffffffffu, s, j + 2 + half);
            int s2 = __shfl_sync(0xffffffffu, s, j + 4 + half);
            int s3 = __shfl_sync(0xffffffffu, s, j + 6 + half);
            float4 v0 = *(const float4*)(y + (size_t)s0 * 64 + c4);
            float4 v1 = *(const float4*)(y + (size_t)s1 * 64 + c4);
            float4 v2 = *(const float4*)(y + (size_t)s2 * 64 + c4);
            float4 v3 = *(const float4*)(y + (size_t)s3 * 64 + c4);
            a0.x += v0.x; a0.y += v0.y; a0.z += v0.z; a0.w += v0.w;
            a1.x += v1.x; a1.y += v1.y; a1.z += v1.z; a1.w += v1.w;
            a2.x += v2.x; a2.y += v2.y; a2.z += v2.z; a2.w += v2.w;
            a3.x += v3.x; a3.y += v3.y; a3.z += v3.z; a3.w += v3.w;
        }
        for (; j + 2 <= m; j += 2) {
            int sj = __shfl_sync(0xffffffffu, s, j + half);
            float4 v = *(const float4*)(y + (size_t)sj * 64 + c4);
            a0.x += v.x; a0.y += v.y; a0.z += v.z; a0.w += v.w;
        }
        if (j < m) {                       // odd leftover: half 0 only
            int sj = __shfl_sync(0xffffffffu, s, j);
            if (half == 0) {
                float4 v = *(const float4*)(y + (size_t)sj * 64 + c4);
                a0.x += v.x; a0.y += v.y; a0.z += v.z; a0.w += v.w;
            }
        }
    }
    float4 acc;
    acc.x = a0.x + a1.x + a2.x + a3.x;
    acc.y = a0.y + a1.y + a2.y + a3.y;
    acc.z = a0.z + a1.z + a2.z + a3.z;
    acc.w = a0.w + a1.w + a2.w + a3.w;
    acc.x += __shfl_xor_sync(0xffffffffu, acc.x, 16);
    acc.y += __shfl_xor_sync(0xffffffffu, acc.y, 16);
    acc.z += __shfl_xor_sync(0xffffffffu, acc.z, 16);
    acc.w += __shfl_xor_sync(0xffffffffu, acc.w, 16);

    if (half == 0) {
        float inv = 1.f / fmaxf((float)(end - beg), 1.f);
        float4 rv = *(const float4*)(r + (size_t)n * 64 + c4);
        float4 bv = *(const float4*)(bl + c4);
        float4 hv;
        hv.x = acc.x * inv + bv.x + rv.x;
        hv.y = acc.y * inv + bv.y + rv.y;
        hv.z = acc.z * inv + bv.z + rv.z;
        hv.w = acc.w * inv + bv.w + rv.w;
        *(float4*)(h + (size_t)n * 64 + c4) = hv;
        atomicAdd(&sbuf[c4 + 0], hv.x);
        atomicAdd(&sbuf[c4 + 1], hv.y);
        atomicAdd(&sbuf[c4 + 2], hv.z);
        atomicAdd(&sbuf[c4 + 3], hv.w);
        atomicAdd(&sbuf[64 + c4 + 0], hv.x * hv.x);
        atomicAdd(&sbuf[64 + c4 + 1], hv.y * hv.y);
        atomicAdd(&sbuf[64 + c4 + 2], hv.z * hv.z);
        atomicAdd(&sbuf[64 + c4 + 3], hv.w * hv.w);
    }
    __syncthreads();
    if (tid < 128) atomicAdd(stats + tid, sbuf[tid]);
}

// ---------------- BN params (also re-zeroes stats for the next layer) --------
__global__ void bn_param_kernel(float* __restrict__ stats,
                                const float* __restrict__ gamma,
                                const float* __restrict__ beta,
                                float* __restrict__ ab) {
    int c = threadIdx.x;  // 64 threads
    float mu = stats[c] * (1.f / (float)NN);
    float var = stats[64 + c] * (1.f / (float)NN) - mu * mu;
    float a = gamma[c] * rsqrtf(var + 1e-5f);
    ab[c] = a;
    ab[64 + c] = beta[c] - a * mu;
    stats[c] = 0.f;
    stats[64 + c] = 0.f;
}

// ---------------- node GEMM on mma.sync: A from global, B via ldmatrix -------
template <int K>
__global__ void __launch_bounds__(256, 3) node_gemm_mma(
    const float* __restrict__ A,
    const float* __restrict__ B1, int ldb1,
    const float* __restrict__ B2, int ldb2,
    int split,
    float* __restrict__ out1, int w1, const float* __restrict__ bias1,
    float* __restrict__ out2, int w2,
    const float* __restrict__ ab)
{
    constexpr int KP = K + 8;                       // padded row (conflict-free)
    extern __shared__ char smem[];
    const int OF_WHI = 0;                           // 128 * KP * 2
    const int OF_WLO = 128 * KP * 2;

    int tid = threadIdx.x, wid = tid >> 5, lane = tid & 31;
    int colBase = blockIdx.y * 128;
    int n0 = blockIdx.x * 128;

    // ---- stage W hi/lo (float4-wise) ----
    for (int i = tid; i < 128 * K / 4; i += 256) {
        int idx = i * 4;
        int o = idx / K, k = idx % K;
        int colg = colBase + o;
        const float* brow = (colg < split) ? (B1 + (size_t)colg * ldb1)
                                           : (B2 + (size_t)(colg - split) * ldb2);
        float4 w4 = *(const float4*)(brow + k);
        uint2 hp, lp;
        split_bf16x4(w4, hp, lp);
        *(uint2*)(smem + OF_WHI + (o * KP + k) * 2) = hp;
        *(uint2*)(smem + OF_WLO + (o * KP + k) * 2) = lp;
    }
    __syncthreads();

    const int r = lane >> 2;           // 0..7
    const int cq = (lane & 3) * 2;     // 0,2,4,6
    int rA = n0 + wid * 16 + r;
    int rB = rA + 8;
    bool okA = rA < NN, okB = rB < NN;
    const float* rowA = A + (size_t)(okA ? rA : 0) * K;
    const float* rowB = A + (size_t)(okB ? rB : 0) * K;

    // ldmatrix lane base: mat 0 = hi@k0, 1 = hi@k0+8, 2 = lo@k0, 3 = lo@k0+8
    uint32_t sbase = smem_u32(smem);
    int mat = lane >> 3, t = lane & 7;
    uint32_t lbase = sbase + ((mat < 2) ? 0u : (uint32_t)OF_WLO)
                   + (uint32_t)t * (KP * 2) + ((mat & 1) ? 16u : 0u);

#pragma unroll
    for (int half = 0; half < 2; half++) {
        float acc[8][4];
#pragma unroll
        for (int n = 0; n < 8; n++)
#pragma unroll
            for (int j = 0; j < 4; j++) acc[n][j] = 0.f;

#pragma unroll
        for (int ks = 0; ks < K / 16; ks++) {
            int k0 = ks * 16;
            // A-frags straight from global + fused affine/ReLU + split
            float2 f0 = okA ? *(const float2*)(rowA + k0 + cq)
                            : make_float2(0.f, 0.f);
            float2 f2 = okA ? *(const float2*)(rowA + k0 + cq + 8)
                            : make_float2(0.f, 0.f);
            float2 f1 = okB ? *(const float2*)(rowB + k0 + cq)
                            : make_float2(0.f, 0.f);
            float2 f3 = okB ? *(const float2*)(rowB + k0 + cq + 8)
                            : make_float2(0.f, 0.f);
            if (ab) {
                int ka = k0 + cq, kb = k0 + cq + 8;
                float a0 = ab[ka], a1 = ab[ka + 1];
                float c0 = ab[64 + ka], c1 = ab[64 + ka + 1];
                float a8 = ab[kb], a9 = ab[kb + 1];
                float c8 = ab[64 + kb], c9 = ab[64 + kb + 1];
                f0.x = fmaxf(a0 * f0.x + c0, 0.f); f0.y = fmaxf(a1 * f0.y + c1, 0.f);
                f1.x = fmaxf(a0 * f1.x + c0, 0.f); f1.y = fmaxf(a1 * f1.y + c1, 0.f);
                f2.x = fmaxf(a8 * f2.x + c8, 0.f); f2.y = fmaxf(a9 * f2.y + c9, 0.f);
                f3.x = fmaxf(a8 * f3.x + c8, 0.f); f3.y = fmaxf(a9 * f3.y + c9, 0.f);
            }
            uint32_t ah0, ah1, ah2, ah3, al0, al1, al2, al3;
            split_bf16x2(f0, ah0, al0);
            split_bf16x2(f1, ah1, al1);
            split_bf16x2(f2, ah2, al2);
            split_bf16x2(f3, ah3, al3);

#pragma unroll
            for (int n = 0; n < 8; n++) {
                int nn = half * 8 + n;
                uint32_t baddr = lbase + (uint32_t)(nn * 8) * (KP * 2)
                               + (uint32_t)k0 * 2;
                uint32_t bh0, bh1, bl0, bl1;
                ldsm_x4(bh0, bh1, bl0, bl1, baddr);
                mma16816(acc[n], ah0, ah1, ah2, ah3, bh0, bh1);
                mma16816(acc[n], al0, al1, al2, al3, bh0, bh1);
                mma16816(acc[n], ah0, ah1, ah2, ah3, bl0, bl1);
            }
        }

        // ---- epilogue for this half: bias + dual-output split ----
#pragma unroll
        for (int n = 0; n < 8; n++) {
            int nn = half * 8 + n;
            int c0g = colBase + nn * 8 + cq;
            float bia0 = 0.f, bia1 = 0.f;
            if (bias1 != nullptr && c0g < split) {
                bia0 = __ldg(bias1 + c0g);
                bia1 = __ldg(bias1 + c0g + 1);
            }
            float* op;
            int lc, w;
            if (c0g < split) { op = out1; lc = c0g; w = w1; }
            else             { op = out2; lc = c0g - split; w = w2; }
            if (okA)
                *(float2*)(op + (size_t)rA * w + lc) =
                    make_float2(acc[n][0] + bia0, acc[n][1] + bia1);
            if (okB)
                *(float2*)(op + (size_t)rB * w + lc) =
                    make_float2(acc[n][2] + bia0, acc[n][3] + bia1);
        }
    }
}

// ---------------- per-edge MLP in CSR order (dst-grouped Q locality) ---------
// Tiles iterate CSR slots; consecutive slots share dst (avg run 16), so
// Q[dst] gathers hit L1/L2 instead of unique L2 lines. ea gathered and out
// scattered by original edge id.
#define KPAD 136                      // bf16 elems per row (272 B, conflict-free)
#define KE 20                         // W1e/ea padded row in bf16 (40 B)
__global__ void __launch_bounds__(256, 2) edge_mlp_mma_kernel(
    const int* __restrict__ csrc, const int* __restrict__ ceid,
    const int* __restrict__ cdst, const float* __restrict__ ea,
    const float* __restrict__ P, const float* __restrict__ Q,
    const float* __restrict__ Wm1, const float* __restrict__ Wm2,
    const float* __restrict__ bm2, const float* __restrict__ Wm3,
    const float* __restrict__ bm3, float* __restrict__ out)
{
    extern __shared__ char smem[];
    const int OF_AHI = 0;                      // 128 * 272 = 34816
    const int OF_ALO = 34816;                  // 34816
    const int OF_BHI = 69632;                  // 64 * 272 = 17408
    const int OF_BLO = 87040;                  // 17408
    const int OF_WEH = 104448;                 // W1e hi: 128 * KE * 2 = 5120
    const int OF_WEL = 109568;                 // W1e lo: 5120
    const int OF_W3  = 114688;                 // 128 fp32 = 512
    const int OF_BM2 = 115200;                 // 64 fp32 = 256
    float* w3s  = (float*)(smem + OF_W3);
    float* bm2s = (float*)(smem + OF_BM2);

    int tid = threadIdx.x, wid = tid >> 5, lane = tid & 31;

    // ---- stage weights once per block ----
    for (int i = tid; i < 128 * 16; i += 256) {
        int j = i >> 4, k = i & 15;
        float w = __ldg(Wm1 + j * 144 + 64 + k);
        __nv_bfloat16 h = __float2bfloat16_rn(w);
        __nv_bfloat16 l = __float2bfloat16_rn(w - __bfloat162float(h));
        *(unsigned short*)(smem + OF_WEH + (j * KE + k) * 2) = __bfloat16_as_ushort(h);
        *(unsigned short*)(smem + OF_WEL + (j * KE + k) * 2) = __bfloat16_as_ushort(l);
    }
    if (tid < 128) { int c = tid >> 1, t = tid & 1; w3s[tid] = __ldg(Wm3 + t * 64 + c); }
    if (tid < 64) bm2s[tid] = __ldg(bm2 + tid);
    for (int i = tid; i < 64 * 128; i += 256) {
        int o = i >> 7, k = i & 127;
        float w = __ldg(Wm2 + o * 128 + k);
        __nv_bfloat16 h = __float2bfloat16_rn(w);
        __nv_bfloat16 l = __float2bfloat16_rn(w - __bfloat162float(h));
        *(unsigned short*)(smem + OF_BHI + (o * KPAD + k) * 2) = __bfloat16_as_ushort(h);
        *(unsigned short*)(smem + OF_BLO + (o * KPAD + k) * 2) = __bfloat16_as_ushort(l);
    }
    __syncthreads();

    const int r = lane >> 2;           // 0..7
    const int cq = (lane & 3) * 2;     // 0,2,4,6
    float b30 = __ldg(bm3), b31 = __ldg(bm3 + 1);

    // ---- persistent loop over CSR-slot tiles ----
    for (int tile = blockIdx.x; tile < NTILES; tile += gridDim.x) {
        int s0 = tile * 128;
        int slotA = s0 + wid * 16 + r;         // frag row r
        int slotB = slotA + 8;                 // frag row r+8
        long long eidA = __ldg(ceid + slotA);
        long long eidB = __ldg(ceid + slotB);

        // phase A1: ea A-frags hi/lo straight from global (rows = CSR slots)
        float2 f0 = *(const float2*)(ea + eidA * 16 + cq);
        float2 f2 = *(const float2*)(ea + eidA * 16 + cq + 8);
        float2 f1 = *(const float2*)(ea + eidB * 16 + cq);
        float2 f3 = *(const float2*)(ea + eidB * 16 + cq + 8);
        uint32_t ah0, ah1, ah2, ah3, al0, al1, al2, al3;
        split_bf16x2(f0, ah0, al0);
        split_bf16x2(f1, ah1, al1);
        split_bf16x2(f2, ah2, al2);
        split_bf16x2(f3, ah3, al3);

        float acc_ea[16][4];
#pragma unroll
        for (int n = 0; n < 16; n++)
#pragma unroll
            for (int j = 0; j < 4; j++) acc_ea[n][j] = 0.f;

#pragma unroll
        for (int n = 0; n < 16; n++) {
            const char* bh = smem + OF_WEH + ((size_t)(n * 8 + r) * KE + cq) * 2;
            const char* bl = smem + OF_WEL + ((size_t)(n * 8 + r) * KE + cq) * 2;
            uint32_t bh0 = *(const uint32_t*)(bh);
            uint32_t bh1 = *(const uint32_t*)(bh + 16);
            uint32_t bl0 = *(const uint32_t*)(bl);
            uint32_t bl1 = *(const uint32_t*)(bl + 16);
            mma16816(acc_ea[n], ah0, ah1, ah2, ah3, bh0, bh1);
            mma16816(acc_ea[n], al0, al1, al2, al3, bh0, bh1);
            mma16816(acc_ea[n], ah0, ah1, ah2, ah3, bl0, bl1);
        }

        // phase A2: gather P[src] (random) + Q[dst] (dst-grouped, L1-warm),
        // combine+ReLU in d-frag layout, split, store panels
        int srcA = __ldg(csrc + slotA);
        int dstA = __ldg(cdst + slotA);
        int srcB = __ldg(csrc + slotB);
        int dstB = __ldg(cdst + slotB);
        const float* PA = P + (size_t)srcA * 128;
        const float* QA = Q + (size_t)dstA * 128;
        const float* PB = P + (size_t)srcB * 128;
        const float* QB = Q + (size_t)dstB * 128;
        int rowA = wid * 16 + r, rowB = rowA + 8;
#pragma unroll
        for (int n = 0; n < 16; n++) {
            int c0 = n * 8 + cq;
            float2 p = *(const float2*)(PA + c0);
            float2 q = *(const float2*)(QA + c0);
            float2 z;
            z.x = fmaxf(acc_ea[n][0] + p.x + q.x, 0.f);
            z.y = fmaxf(acc_ea[n][1] + p.y + q.y, 0.f);
            uint32_t h, l;
            split_bf16x2(z, h, l);
            *(uint32_t*)(smem + OF_AHI + ((size_t)rowA * KPAD + c0) * 2) = h;
            *(uint32_t*)(smem + OF_ALO + ((size_t)rowA * KPAD + c0) * 2) = l;
            p = *(const float2*)(PB + c0);
            q = *(const float2*)(QB + c0);
            z.x = fmaxf(acc_ea[n][2] + p.x + q.x, 0.f);
            z.y = fmaxf(acc_ea[n][3] + p.y + q.y, 0.f);
            split_bf16x2(z, h, l);
            *(uint32_t*)(smem + OF_AHI + ((size_t)rowB * KPAD + c0) * 2) = h;
            *(uint32_t*)(smem + OF_ALO + ((size_t)rowB * KPAD + c0) * 2) = l;
        }
        __syncthreads();

        // phase B: GEMM2, warp w -> 16 slots x 64 outs
        float acc[8][4];
#pragma unroll
        for (int n = 0; n < 8; n++)
#pragma unroll
            for (int j = 0; j < 4; j++) acc[n][j] = 0.f;

#pragma unroll
        for (int term = 0; term < 3; term++) {
            const char* Abuf = smem + ((term == 1) ? OF_ALO : OF_AHI);
            const char* Bbuf = smem + ((term == 2) ? OF_BLO : OF_BHI);
#pragma unroll
            for (int ks = 0; ks < 8; ks++) {
                int k0 = ks * 16;
                const char* ab = Abuf + (size_t)(wid * 16 + r) * (KPAD * 2)
                               + (k0 + cq) * 2;
                uint32_t a0 = *(const uint32_t*)(ab);
                uint32_t a1 = *(const uint32_t*)(ab + 8 * (KPAD * 2));
                uint32_t a2 = *(const uint32_t*)(ab + 16);
                uint32_t a3 = *(const uint32_t*)(ab + 8 * (KPAD * 2) + 16);
#pragma unroll
                for (int n = 0; n < 8; n++) {
                    const char* bb = Bbuf + (size_t)(n * 8 + r) * (KPAD * 2)
                                   + (k0 + cq) * 2;
                    uint32_t b0 = *(const uint32_t*)(bb);
                    uint32_t b1 = *(const uint32_t*)(bb + 16);
                    mma16816(acc[n], a0, a1, a2, a3, b0, b1);
                }
            }
        }

        // epilogue: bias+ReLU+layer3; scatter by original edge id
        float oa0 = 0.f, oa1 = 0.f, ob0 = 0.f, ob1 = 0.f;
#pragma unroll
        for (int n = 0; n < 8; n++) {
            int c0 = n * 8 + cq, c1 = c0 + 1;
            float w300 = w3s[2 * c0], w301 = w3s[2 * c0 + 1];
            float w310 = w3s[2 * c1], w311 = w3s[2 * c1 + 1];
            float bb0 = bm2s[c0], bb1 = bm2s[c1];
            float z;
            z = fmaxf(acc[n][0] + bb0, 0.f); oa0 += z * w300; oa1 += z * w301;
            z = fmaxf(acc[n][1] + bb1, 0.f); oa0 += z * w310; oa1 += z * w311;
            z = fmaxf(acc[n][2] + bb0, 0.f); ob0 += z * w300; ob1 += z * w301;
            z = fmaxf(acc[n][3] + bb1, 0.f); ob0 += z * w310; ob1 += z * w311;
        }
#pragma unroll
        for (int off = 1; off <= 2; off <<= 1) {
            oa0 += __shfl_xor_sync(0xffffffffu, oa0, off);
            oa1 += __shfl_xor_sync(0xffffffffu, oa1, off);
            ob0 += __shfl_xor_sync(0xffffffffu, ob0, off);
            ob1 += __shfl_xor_sync(0xffffffffu, ob1, off);
        }
        if ((lane & 3) == 0) {
            *(float2*)(out + eidA * 2) = make_float2(oa0 + b30, oa1 + b31);
            *(float2*)(out + eidB * 2) = make_float2(ob0 + b30, ob1 + b31);
        }
        __syncthreads();   // panels reused next tile
    }
}

// ---------------- host orchestration ----------------------------------------
extern "C" void kernel_launch(void* const* d_in, const int* in_sizes, int n_in,
                              void* d_out, int out_size)
{
    (void)in_sizes; (void)n_in; (void)out_size;
    const float* x   = (const float*)d_in[0];
    const void*  ei  = d_in[1];
    const float* ea  = (const float*)d_in[2];
    const float* W1l = (const float*)d_in[3];
    const float* b1l = (const float*)d_in[4];
    const float* W1r = (const float*)d_in[5];
    const float* g1  = (const float*)d_in[6];
    const float* be1 = (const float*)d_in[7];
    const float* W2l = (const float*)d_in[8];
    const float* b2l = (const float*)d_in[9];
    const float* W2r = (const float*)d_in[10];
    const float* g2  = (const float*)d_in[11];
    const float* be2 = (const float*)d_in[12];
    const float* Wm1 = (const float*)d_in[13];
    const float* bm1 = (const float*)d_in[14];
    const float* Wm2 = (const float*)d_in[15];
    const float* bm2 = (const float*)d_in[16];
    const float* Wm3 = (const float*)d_in[17];
    const float* bm3 = (const float*)d_in[18];
    float* out = (float*)d_out;

    float *pY, *pR, *pH, *pStats, *pAb, *pP, *pQ;
    int *pDeg, *pOff, *pFill, *pCsr, *pEid, *pCdst;
    cudaGetSymbolAddress((void**)&pY, g_y);
    cudaGetSymbolAddress((void**)&pR, g_r);
    cudaGetSymbolAddress((void**)&pH, g_h);
    cudaGetSymbolAddress((void**)&pStats, g_stats);
    cudaGetSymbolAddress((void**)&pAb, g_ab);
    cudaGetSymbolAddress((void**)&pP, g_P);
    cudaGetSymbolAddress((void**)&pQ, g_Q);
    cudaGetSymbolAddress((void**)&pDeg, g_deg);
    cudaGetSymbolAddress((void**)&pOff, g_off);
    cudaGetSymbolAddress((void**)&pFill, g_fill);
    cudaGetSymbolAddress((void**)&pCsr, g_csr);
    cudaGetSymbolAddress((void**)&pEid, g_eid);
    cudaGetSymbolAddress((void**)&pCdst, g_cdst);

    const int smemG128 = 128 * 136 * 2 * 2;   // 69632 (W panels only)
    const int smemG64  = 128 * 72 * 2 * 2;    // 36864
    const int smemEdge = 115456;
    cudaFuncSetAttribute(node_gemm_mma<128>, cudaFuncAttributeMaxDynamicSharedMemorySize, smemG128);
    cudaFuncSetAttribute(node_gemm_mma<64>,  cudaFuncAttributeMaxDynamicSharedMemorySize, smemG64);
    cudaFuncSetAttribute(edge_mlp_mma_kernel, cudaFuncAttributeMaxDynamicSharedMemorySize, smemEdge);

    const int NROW_TILES = (NN + 127) / 128;   // 391

    // ---- prologue (gemm128 stays in the profiled 4th-kernel slot) ----
    init_kernel<<<(NN + 255) / 256, 256>>>(ei, pDeg, pFill, pStats); // k1
    hist_kernel<<<(EE + 255) / 256, 256>>>(ei, pDeg);                // k2
    scan_kernel<<<1, 1024>>>(pDeg, pOff);                            // k3
    node_gemm_mma<128><<<dim3(NROW_TILES, 1), 256, smemG128>>>(      // k4 (prof)
        x, W1l, 128, W1r, 128, 64, pY, 64, nullptr, pR, 64, nullptr);
    csr_fill_kernel<<<(EE + 255) / 256, 256>>>(ei, pOff, pFill, pCsr, pEid, pCdst);

    // ---- layer 1 aggregate + BN ----
    aggregate_kernel<<<NN / 8, 256>>>(pOff, pCsr, pY, pR, b1l, pH, pStats);
    bn_param_kernel<<<1, 64>>>(pStats, g1, be1, pAb);   // also re-zeroes stats

    // ---- layer 2 ----
    node_gemm_mma<64><<<dim3(NROW_TILES, 1), 256, smemG64>>>(
        pH, W2l, 64, W2r, 64, 64, pY, 64, nullptr, pR, 64, pAb);
    aggregate_kernel<<<NN / 8, 256>>>(pOff, pCsr, pY, pR, b2l, pH, pStats);
    bn_param_kernel<<<1, 64>>>(pStats, g2, be2, pAb + 128);

    // ---- node precompute for edge MLP: P (with bm1) and Q ----
    node_gemm_mma<64><<<dim3(NROW_TILES, 2), 256, smemG64>>>(
        pH, Wm1, 144, Wm1 + 80, 144, 128, pP, 128, bm1, pQ, 128, pAb + 128);

    // ---- per-edge MLP in CSR order on tensor cores (persistent) ----
    edge_mlp_mma_kernel<<<PERSIST_BLOCKS, 256, smemEdge>>>(
        pCsr, pEid, pCdst, ea, pP, pQ, Wm1, Wm2, bm2, Wm3, bm3, out);
}

// round 15
// speedup vs baseline: 1.1299x; 1.1299x over previous
#include <cuda_runtime.h>
#include <cuda_bf16.h>
#include <cstdint>
#include <math.h>

#define NN 50000
#define EE 800000
#define NTILES (EE / 128)          // 6250 edge tiles
#define PERSIST_BLOCKS 296         // 148 SMs x 2 blocks

// ---------------- scratch (device globals; no allocations allowed) ----------
__device__ float g_y[NN * 64];      // messages y = h @ Wl^T
__device__ float g_r[NN * 64];      // root    r = h @ Wr^T
__device__ float g_h[NN * 64];      // pre-BN hidden
__device__ float g_stats[128];      // per-channel sum / sumsq
__device__ float g_ab[256];         // BN affine: [a1|c1|a2|c2]
__device__ float g_P[NN * 128];     // P = hf @ Wm1[:, :64]^T + bm1
__device__ float g_Q[NN * 128];     // Q = hf @ Wm1[:, 80:]^T
__device__ int   g_deg[NN];         // in-degree
__device__ int   g_off[NN + 1];     // CSR offsets
__device__ int   g_fill[NN];        // fill cursors
__device__ int   g_csr[EE];         // src node per CSR slot (grouped by dst)
__device__ int   g_idx64;           // 1 if edge_index is int64, 0 if int32

// ---------------- portable bf16 HMMA (sm_80+ PTX, works on compute_103) -----
__device__ __forceinline__ void mma16816(float* d,
                                         uint32_t a0, uint32_t a1,
                                         uint32_t a2, uint32_t a3,
                                         uint32_t b0, uint32_t b1) {
    asm volatile(
        "mma.sync.aligned.m16n8k16.row.col.f32.bf16.bf16.f32 "
        "{%0,%1,%2,%3}, {%4,%5,%6,%7}, {%8,%9}, {%0,%1,%2,%3};"
        : "+f"(d[0]), "+f"(d[1]), "+f"(d[2]), "+f"(d[3])
        : "r"(a0), "r"(a1), "r"(a2), "r"(a3), "r"(b0), "r"(b1));
}

__device__ __forceinline__ void ldsm_x4(uint32_t& r0, uint32_t& r1,
                                        uint32_t& r2, uint32_t& r3,
                                        uint32_t addr) {
    asm volatile(
        "ldmatrix.sync.aligned.m8n8.x4.shared.b16 {%0,%1,%2,%3}, [%4];"
        : "=r"(r0), "=r"(r1), "=r"(r2), "=r"(r3) : "r"(addr));
}

__device__ __forceinline__ uint32_t smem_u32(const void* p) {
    return (uint32_t)__cvta_generic_to_shared(p);
}

__device__ __forceinline__ void split_bf16x2(float2 v, uint32_t& h, uint32_t& l) {
    __nv_bfloat16 h0 = __float2bfloat16_rn(v.x);
    __nv_bfloat16 h1 = __float2bfloat16_rn(v.y);
    __nv_bfloat16 l0 = __float2bfloat16_rn(v.x - __bfloat162float(h0));
    __nv_bfloat16 l1 = __float2bfloat16_rn(v.y - __bfloat162float(h1));
    h = ((uint32_t)__bfloat16_as_ushort(h1) << 16) | __bfloat16_as_ushort(h0);
    l = ((uint32_t)__bfloat16_as_ushort(l1) << 16) | __bfloat16_as_ushort(l0);
}

__device__ __forceinline__ void split_bf16x4(float4 v, uint2& hp, uint2& lp) {
    split_bf16x2(make_float2(v.x, v.y), hp.x, lp.x);
    split_bf16x2(make_float2(v.z, v.w), hp.y, lp.y);
}

// ---------------- init: zero deg/fill/stats + dtype detection ----------------
__global__ void init_kernel(const void* ei, int* __restrict__ deg,
                            int* __restrict__ fill, float* __restrict__ stats) {
    int i = blockIdx.x * blockDim.x + threadIdx.x;
    if (i < NN) { deg[i] = 0; fill[i] = 0; }
    if (i < 128) stats[i] = 0.f;
    if (i == 0) {
        const unsigned int* w = (const unsigned int*)ei;
        int f = 1;
        for (int k = 0; k < 32; k++)
            if (w[2 * k + 1] != 0u) f = 0;   // int32 data: odd words random
        g_idx64 = f;
    }
}

__device__ __forceinline__ int load_idx(const void* ei, long long i, int is64) {
    if (is64) return (int)__ldg(((const long long*)ei) + i);
    return __ldg(((const int*)ei) + i);
}

// ---------------- CSR build --------------------------------------------------
__global__ void hist_kernel(const void* __restrict__ ei, int* __restrict__ deg) {
    int e = blockIdx.x * blockDim.x + threadIdx.x;
    if (e >= EE) return;
    int dst = load_idx(ei, (long long)EE + e, g_idx64);
    atomicAdd(deg + dst, 1);
}

__global__ void scan_kernel(const int* __restrict__ deg, int* __restrict__ off) {
    __shared__ int part[1024];
    int tid = threadIdx.x;                 // 1024 threads, 1 block
    const int CH = (NN + 1023) / 1024;     // 49
    int s0 = tid * CH;
    int lsum = 0;
    for (int i = 0; i < CH; i++) {
        int idx = s0 + i;
        if (idx < NN) lsum += deg[idx];
    }
    part[tid] = lsum;
    __syncthreads();
    for (int d = 1; d < 1024; d <<= 1) {
        int v = (tid >= d) ? part[tid - d] : 0;
        __syncthreads();
        part[tid] += v;
        __syncthreads();
    }
    int run = (tid == 0) ? 0 : part[tid - 1];
    for (int i = 0; i < CH; i++) {
        int idx = s0 + i;
        if (idx < NN) { off[idx] = run; run += deg[idx]; }
    }
    if (tid == 1023) off[NN] = run;
}

__global__ void csr_fill_kernel(const void* __restrict__ ei,
                                const int* __restrict__ off,
                                int* __restrict__ fill,
                                int* __restrict__ csr) {
    int e = blockIdx.x * blockDim.x + threadIdx.x;
    if (e >= EE) return;
    int is64 = g_idx64;
    int src = load_idx(ei, e, is64);
    int dst = load_idx(ei, (long long)EE + e, is64);
    int slot = off[dst] + atomicAdd(fill + dst, 1);
    csr[slot] = src;
}

// ---------------- aggregate + finalize + BN stats (half-warp float4) ---------
__global__ void aggregate_kernel(const int* __restrict__ off,
                                 const int* __restrict__ csr,
                                 const float* __restrict__ y,
                                 const float* __restrict__ r,
                                 const float* __restrict__ bl,
                                 float* __restrict__ h,
                                 float* __restrict__ stats) {
    __shared__ float sbuf[128];
    int tid = threadIdx.x;
    int lane = tid & 31, wid = tid >> 5;
    if (tid < 128) sbuf[tid] = 0.f;
    __syncthreads();

    int n = blockIdx.x * 8 + wid;          // 8 warps = 8 nodes per block
    int beg = off[n], end = off[n + 1];
    int half = lane >> 4;                  // 0 or 1
    int c4 = (lane & 15) * 4;              // channel base
    float4 a0 = make_float4(0.f, 0.f, 0.f, 0.f);
    float4 a1 = make_float4(0.f, 0.f, 0.f, 0.f);
    float4 a2 = make_float4(0.f, 0.f, 0.f, 0.f);
    float4 a3 = make_float4(0.f, 0.f, 0.f, 0.f);

    for (int base = beg; base < end; base += 32) {
        int idx = base + lane;
        int s = (idx < end) ? __ldg(csr + idx) : 0;
        int m = min(32, end - base);
        int j = 0;
        for (; j + 8 <= m; j += 8) {
            int s0 = __shfl_sync(0xffffffffu, s, j + half);
            int s1 = __shfl_sync(0xffffffffu, s, j + 2 + half);
            int s2 = __shfl_sync(0xffffffffu, s, j + 4 + half);
            int s3 = __shfl_sync(0xffffffffu, s, j + 6 + half);
            float4 v0 = *(const float4*)(y + (size_t)s0 * 64 + c4);
            float4 v1 = *(const float4*)(y + (size_t)s1 * 64 + c4);
            float4 v2 = *(const float4*)(y + (size_t)s2 * 64 + c4);
            float4 v3 = *(const float4*)(y + (size_t)s3 * 64 + c4);
            a0.x += v0.x; a0.y += v0.y; a0.z += v0.z; a0.w += v0.w;
            a1.x += v1.x; a1.y += v1.y; a1.z += v1.z; a1.w += v1.w;
            a2.x += v2.x; a2.y += v2.y; a2.z += v2.z; a2.w += v2.w;
            a3.x += v3.x; a3.y += v3.y; a3.z += v3.z; a3.w += v3.w;
        }
        for (; j + 2 <= m; j += 2) {
            int sj = __shfl_sync(0xffffffffu, s, j + half);
            float4 v = *(const float4*)(y + (size_t)sj * 64 + c4);
            a0.x += v.x; a0.y += v.y; a0.z += v.z; a0.w += v.w;
        }
        if (j < m) {                       // odd leftover: half 0 only
            int sj = __shfl_sync(0xffffffffu, s, j);
            if (half == 0) {
                float4 v = *(const float4*)(y + (size_t)sj * 64 + c4);
                a0.x += v.x; a0.y += v.y; a0.z += v.z; a0.w += v.w;
            }
        }
    }
    float4 acc;
    acc.x = a0.x + a1.x + a2.x + a3.x;
    acc.y = a0.y + a1.y + a2.y + a3.y;
    acc.z = a0.z + a1.z + a2.z + a3.z;
    acc.w = a0.w + a1.w + a2.w + a3.w;
    acc.x += __shfl_xor_sync(0xffffffffu, acc.x, 16);
    acc.y += __shfl_xor_sync(0xffffffffu, acc.y, 16);
    acc.z += __shfl_xor_sync(0xffffffffu, acc.z, 16);
    acc.w += __shfl_xor_sync(0xffffffffu, acc.w, 16);

    if (half == 0) {
        float inv = 1.f / fmaxf((float)(end - beg), 1.f);
        float4 rv = *(const float4*)(r + (size_t)n * 64 + c4);
        float4 bv = *(const float4*)(bl + c4);
        float4 hv;
        hv.x = acc.x * inv + bv.x + rv.x;
        hv.y = acc.y * inv + bv.y + rv.y;
        hv.z = acc.z * inv + bv.z + rv.z;
        hv.w = acc.w * inv + bv.w + rv.w;
        *(float4*)(h + (size_t)n * 64 + c4) = hv;
        atomicAdd(&sbuf[c4 + 0], hv.x);
        atomicAdd(&sbuf[c4 + 1], hv.y);
        atomicAdd(&sbuf[c4 + 2], hv.z);
        atomicAdd(&sbuf[c4 + 3], hv.w);
        atomicAdd(&sbuf[64 + c4 + 0], hv.x * hv.x);
        atomicAdd(&sbuf[64 + c4 + 1], hv.y * hv.y);
        atomicAdd(&sbuf[64 + c4 + 2], hv.z * hv.z);
        atomicAdd(&sbuf[64 + c4 + 3], hv.w * hv.w);
    }
    __syncthreads();
    if (tid < 128) atomicAdd(stats + tid, sbuf[tid]);
}

// ---------------- BN params (also re-zeroes stats for the next layer) --------
__global__ void bn_param_kernel(float* __restrict__ stats,
                                const float* __restrict__ gamma,
                                const float* __restrict__ beta,
                                float* __restrict__ ab) {
    int c = threadIdx.x;  // 64 threads
    float mu = stats[c] * (1.f / (float)NN);
    float var = stats[64 + c] * (1.f / (float)NN) - mu * mu;
    float a = gamma[c] * rsqrtf(var + 1e-5f);
    ab[c] = a;
    ab[64 + c] = beta[c] - a * mu;
    stats[c] = 0.f;
    stats[64 + c] = 0.f;
}

// ---------------- node GEMM on mma.sync: A from global, B via ldmatrix -------
template <int K>
__global__ void __launch_bounds__(256, 3) node_gemm_mma(
    const float* __restrict__ A,
    const float* __restrict__ B1, int ldb1,
    const float* __restrict__ B2, int ldb2,
    int split,
    float* __restrict__ out1, int w1, const float* __restrict__ bias1,
    float* __restrict__ out2, int w2,
    const float* __restrict__ ab)
{
    constexpr int KP = K + 8;                       // padded row (conflict-free)
    extern __shared__ char smem[];
    const int OF_WHI = 0;                           // 128 * KP * 2
    const int OF_WLO = 128 * KP * 2;

    int tid = threadIdx.x, wid = tid >> 5, lane = tid & 31;
    int colBase = blockIdx.y * 128;
    int n0 = blockIdx.x * 128;

    // ---- stage W hi/lo (float4-wise) ----
    for (int i = tid; i < 128 * K / 4; i += 256) {
        int idx = i * 4;
        int o = idx / K, k = idx % K;
        int colg = colBase + o;
        const float* brow = (colg < split) ? (B1 + (size_t)colg * ldb1)
                                           : (B2 + (size_t)(colg - split) * ldb2);
        float4 w4 = *(const float4*)(brow + k);
        uint2 hp, lp;
        split_bf16x4(w4, hp, lp);
        *(uint2*)(smem + OF_WHI + (o * KP + k) * 2) = hp;
        *(uint2*)(smem + OF_WLO + (o * KP + k) * 2) = lp;
    }
    __syncthreads();

    const int r = lane >> 2;           // 0..7
    const int cq = (lane & 3) * 2;     // 0,2,4,6
    int rA = n0 + wid * 16 + r;
    int rB = rA + 8;
    bool okA = rA < NN, okB = rB < NN;
    const float* rowA = A + (size_t)(okA ? rA : 0) * K;
    const float* rowB = A + (size_t)(okB ? rB : 0) * K;

    // ldmatrix lane base: mat 0 = hi@k0, 1 = hi@k0+8, 2 = lo@k0, 3 = lo@k0+8
    uint32_t sbase = smem_u32(smem);
    int mat = lane >> 3, t = lane & 7;
    uint32_t lbase = sbase + ((mat < 2) ? 0u : (uint32_t)OF_WLO)
                   + (uint32_t)t * (KP * 2) + ((mat & 1) ? 16u : 0u);

#pragma unroll
    for (int half = 0; half < 2; half++) {
        float acc[8][4];
#pragma unroll
        for (int n = 0; n < 8; n++)
#pragma unroll
            for (int j = 0; j < 4; j++) acc[n][j] = 0.f;

#pragma unroll
        for (int ks = 0; ks < K / 16; ks++) {
            int k0 = ks * 16;
            // A-frags straight from global + fused affine/ReLU + split
            float2 f0 = okA ? *(const float2*)(rowA + k0 + cq)
                            : make_float2(0.f, 0.f);
            float2 f2 = okA ? *(const float2*)(rowA + k0 + cq + 8)
                            : make_float2(0.f, 0.f);
            float2 f1 = okB ? *(const float2*)(rowB + k0 + cq)
                            : make_float2(0.f, 0.f);
            float2 f3 = okB ? *(const float2*)(rowB + k0 + cq + 8)
                            : make_float2(0.f, 0.f);
            if (ab) {
                int ka = k0 + cq, kb = k0 + cq + 8;
                float a0 = ab[ka], a1 = ab[ka + 1];
                float c0 = ab[64 + ka], c1 = ab[64 + ka + 1];
                float a8 = ab[kb], a9 = ab[kb + 1];
                float c8 = ab[64 + kb], c9 = ab[64 + kb + 1];
                f0.x = fmaxf(a0 * f0.x + c0, 0.f); f0.y = fmaxf(a1 * f0.y + c1, 0.f);
                f1.x = fmaxf(a0 * f1.x + c0, 0.f); f1.y = fmaxf(a1 * f1.y + c1, 0.f);
                f2.x = fmaxf(a8 * f2.x + c8, 0.f); f2.y = fmaxf(a9 * f2.y + c9, 0.f);
                f3.x = fmaxf(a8 * f3.x + c8, 0.f); f3.y = fmaxf(a9 * f3.y + c9, 0.f);
            }
            uint32_t ah0, ah1, ah2, ah3, al0, al1, al2, al3;
            split_bf16x2(f0, ah0, al0);
            split_bf16x2(f1, ah1, al1);
            split_bf16x2(f2, ah2, al2);
            split_bf16x2(f3, ah3, al3);

#pragma unroll
            for (int n = 0; n < 8; n++) {
                int nn = half * 8 + n;
                uint32_t baddr = lbase + (uint32_t)(nn * 8) * (KP * 2)
                               + (uint32_t)k0 * 2;
                uint32_t bh0, bh1, bl0, bl1;
                ldsm_x4(bh0, bh1, bl0, bl1, baddr);
                mma16816(acc[n], ah0, ah1, ah2, ah3, bh0, bh1);
                mma16816(acc[n], al0, al1, al2, al3, bh0, bh1);
                mma16816(acc[n], ah0, ah1, ah2, ah3, bl0, bl1);
            }
        }

        // ---- epilogue for this half: bias + dual-output split ----
#pragma unroll
        for (int n = 0; n < 8; n++) {
            int nn = half * 8 + n;
            int c0g = colBase + nn * 8 + cq;
            float bia0 = 0.f, bia1 = 0.f;
            if (bias1 != nullptr && c0g < split) {
                bia0 = __ldg(bias1 + c0g);
                bia1 = __ldg(bias1 + c0g + 1);
            }
            float* op;
            int lc, w;
            if (c0g < split) { op = out1; lc = c0g; w = w1; }
            else             { op = out2; lc = c0g - split; w = w2; }
            if (okA)
                *(float2*)(op + (size_t)rA * w + lc) =
                    make_float2(acc[n][0] + bia0, acc[n][1] + bia1);
            if (okB)
                *(float2*)(op + (size_t)rB * w + lc) =
                    make_float2(acc[n][2] + bia0, acc[n][3] + bia1);
        }
    }
}

// ---------------- per-edge MLP: BOTH layers on mma.sync (ldmatrix GEMM2) -----
#define KPAD 136                      // bf16 elems per row (272 B, conflict-free)
#define KE 20                         // W1e/ea padded row in bf16 (40 B)
__global__ void __launch_bounds__(256, 2) edge_mlp_mma_kernel(
    const void* __restrict__ ei, const float* __restrict__ ea,
    const float* __restrict__ P, const float* __restrict__ Q,
    const float* __restrict__ Wm1, const float* __restrict__ Wm2,
    const float* __restrict__ bm2, const float* __restrict__ Wm3,
    const float* __restrict__ bm3, float* __restrict__ out)
{
    extern __shared__ char smem[];
    const int OF_AHI = 0;                      // 128 * 272 = 34816
    const int OF_ALO = 34816;                  // 34816
    const int OF_BHI = 69632;                  // 64 * 272 = 17408
    const int OF_BLO = 87040;                  // 17408
    const int OF_WEH = 104448;                 // W1e hi: 128 * KE * 2 = 5120
    const int OF_WEL = 109568;                 // W1e lo: 5120
    const int OF_W3  = 114688;                 // 128 fp32 = 512
    const int OF_BM2 = 115200;                 // 64 fp32 = 256
    float* w3s  = (float*)(smem + OF_W3);
    float* bm2s = (float*)(smem + OF_BM2);

    int tid = threadIdx.x, wid = tid >> 5, lane = tid & 31;
    int is64 = g_idx64;

    // ---- stage weights once per block ----
    for (int i = tid; i < 128 * 16; i += 256) {
        int j = i >> 4, k = i & 15;
        float w = __ldg(Wm1 + j * 144 + 64 + k);
        __nv_bfloat16 h = __float2bfloat16_rn(w);
        __nv_bfloat16 l = __float2bfloat16_rn(w - __bfloat162float(h));
        *(unsigned short*)(smem + OF_WEH + (j * KE + k) * 2) = __bfloat16_as_ushort(h);
        *(unsigned short*)(smem + OF_WEL + (j * KE + k) * 2) = __bfloat16_as_ushort(l);
    }
    if (tid < 128) { int c = tid >> 1, t = tid & 1; w3s[tid] = __ldg(Wm3 + t * 64 + c); }
    if (tid < 64) bm2s[tid] = __ldg(bm2 + tid);
    for (int i = tid; i < 64 * 128; i += 256) {
        int o = i >> 7, k = i & 127;
        float w = __ldg(Wm2 + o * 128 + k);
        __nv_bfloat16 h = __float2bfloat16_rn(w);
        __nv_bfloat16 l = __float2bfloat16_rn(w - __bfloat162float(h));
        *(unsigned short*)(smem + OF_BHI + (o * KPAD + k) * 2) = __bfloat16_as_ushort(h);
        *(unsigned short*)(smem + OF_BLO + (o * KPAD + k) * 2) = __bfloat16_as_ushort(l);
    }
    __syncthreads();

    const int r = lane >> 2;           // 0..7
    const int cq = (lane & 3) * 2;     // 0,2,4,6
    float b30 = __ldg(bm3), b31 = __ldg(bm3 + 1);

    // ldmatrix lane bases for phase B:
    // B: mat 0 = hi@k0, 1 = hi@k0+8, 2 = lo@k0, 3 = lo@k0+8 (rows = out cols)
    // A: mat 0 = rows+0@k0, 1 = rows+8@k0, 2 = rows+0@k0+8, 3 = rows+8@k0+8
    uint32_t sbase = smem_u32(smem);
    int mat = lane >> 3, lt = lane & 7;
    uint32_t bBase = sbase + ((mat < 2) ? (uint32_t)OF_BHI : (uint32_t)OF_BLO)
                   + (uint32_t)lt * (KPAD * 2) + ((mat & 1) ? 16u : 0u);
    uint32_t aRow = (uint32_t)(wid * 16 + ((mat & 1) ? 8 : 0) + lt);
    uint32_t aKoff = (uint32_t)(mat >> 1) * 16u;
    uint32_t aHiBase = sbase + (uint32_t)OF_AHI + aRow * (KPAD * 2) + aKoff;
    uint32_t aLoBase = sbase + (uint32_t)OF_ALO + aRow * (KPAD * 2) + aKoff;

    // ---- persistent loop over edge tiles ----
    for (int tile = blockIdx.x; tile < NTILES; tile += gridDim.x) {
        long long e0 = (long long)tile * 128;
        long long eA = e0 + wid * 16 + r;      // frag row r
        long long eB = eA + 8;                 // frag row r+8

        // phase A1: ea A-frags hi/lo straight from global
        float2 f0 = *(const float2*)(ea + (size_t)eA * 16 + cq);
        float2 f2 = *(const float2*)(ea + (size_t)eA * 16 + cq + 8);
        float2 f1 = *(const float2*)(ea + (size_t)eB * 16 + cq);
        float2 f3 = *(const float2*)(ea + (size_t)eB * 16 + cq + 8);
        uint32_t ah0, ah1, ah2, ah3, al0, al1, al2, al3;
        split_bf16x2(f0, ah0, al0);
        split_bf16x2(f1, ah1, al1);
        split_bf16x2(f2, ah2, al2);
        split_bf16x2(f3, ah3, al3);

        float acc_ea[16][4];
#pragma unroll
        for (int n = 0; n < 16; n++)
#pragma unroll
            for (int j = 0; j < 4; j++) acc_ea[n][j] = 0.f;

#pragma unroll
        for (int n = 0; n < 16; n++) {
            const char* bh = smem + OF_WEH + ((size_t)(n * 8 + r) * KE + cq) * 2;
            const char* bl = smem + OF_WEL + ((size_t)(n * 8 + r) * KE + cq) * 2;
            uint32_t bh0 = *(const uint32_t*)(bh);
            uint32_t bh1 = *(const uint32_t*)(bh + 16);
            uint32_t bl0 = *(const uint32_t*)(bl);
            uint32_t bl1 = *(const uint32_t*)(bl + 16);
            mma16816(acc_ea[n], ah0, ah1, ah2, ah3, bh0, bh1);
            mma16816(acc_ea[n], al0, al1, al2, al3, bh0, bh1);
            mma16816(acc_ea[n], ah0, ah1, ah2, ah3, bl0, bl1);
        }

        // phase A2: gather P/Q in d-frag layout, combine+ReLU, split, store
        int srcA = load_idx(ei, eA, is64);
        int dstA = load_idx(ei, (long long)EE + eA, is64);
        int srcB = load_idx(ei, eB, is64);
        int dstB = load_idx(ei, (long long)EE + eB, is64);
        const float* PA = P + (size_t)srcA * 128;
        const float* QA = Q + (size_t)dstA * 128;
        const float* PB = P + (size_t)srcB * 128;
        const float* QB = Q + (size_t)dstB * 128;
        int rowA = wid * 16 + r, rowB = rowA + 8;
#pragma unroll
        for (int n = 0; n < 16; n++) {
            int c0 = n * 8 + cq;
            float2 p = *(const float2*)(PA + c0);
            float2 q = *(const float2*)(QA + c0);
            float2 z;
            z.x = fmaxf(acc_ea[n][0] + p.x + q.x, 0.f);
            z.y = fmaxf(acc_ea[n][1] + p.y + q.y, 0.f);
            uint32_t h, l;
            split_bf16x2(z, h, l);
            *(uint32_t*)(smem + OF_AHI + ((size_t)rowA * KPAD + c0) * 2) = h;
            *(uint32_t*)(smem + OF_ALO + ((size_t)rowA * KPAD + c0) * 2) = l;
            p = *(const float2*)(PB + c0);
            q = *(const float2*)(QB + c0);
            z.x = fmaxf(acc_ea[n][2] + p.x + q.x, 0.f);
            z.y = fmaxf(acc_ea[n][3] + p.y + q.y, 0.f);
            split_bf16x2(z, h, l);
            *(uint32_t*)(smem + OF_AHI + ((size_t)rowB * KPAD + c0) * 2) = h;
            *(uint32_t*)(smem + OF_ALO + ((size_t)rowB * KPAD + c0) * 2) = l;
        }
        __syncthreads();

        // phase B: GEMM2 via ldmatrix, warp w -> 16 edges x 64 outs
        float acc[8][4];
#pragma unroll
        for (int n = 0; n < 8; n++)
#pragma unroll
            for (int j = 0; j < 4; j++) acc[n][j] = 0.f;

#pragma unroll
        for (int ks = 0; ks < 8; ks++) {
            uint32_t k2 = (uint32_t)(ks * 32);      // k0 * 2 bytes
            uint32_t zh0, zh1, zh2, zh3, zl0, zl1, zl2, zl3;
            ldsm_x4(zh0, zh1, zh2, zh3, aHiBase + k2);
            ldsm_x4(zl0, zl1, zl2, zl3, aLoBase + k2);
#pragma unroll
            for (int n = 0; n < 8; n++) {
                uint32_t baddr = bBase + (uint32_t)(n * 8) * (KPAD * 2) + k2;
                uint32_t bh0, bh1, bl0, bl1;
                ldsm_x4(bh0, bh1, bl0, bl1, baddr);
                mma16816(acc[n], zh0, zh1, zh2, zh3, bh0, bh1);
                mma16816(acc[n], zl0, zl1, zl2, zl3, bh0, bh1);
                mma16816(acc[n], zh0, zh1, zh2, zh3, bl0, bl1);
            }
        }

        // epilogue: bias+ReLU+layer3; d-frag rows {r, r+8}, cols {c, c+1}
        float oa0 = 0.f, oa1 = 0.f, ob0 = 0.f, ob1 = 0.f;
#pragma unroll
        for (int n = 0; n < 8; n++) {
            int c0 = n * 8 + cq, c1 = c0 + 1;
            float w300 = w3s[2 * c0], w301 = w3s[2 * c0 + 1];
            float w310 = w3s[2 * c1], w311 = w3s[2 * c1 + 1];
            float bb0 = bm2s[c0], bb1 = bm2s[c1];
            float z;
            z = fmaxf(acc[n][0] + bb0, 0.f); oa0 += z * w300; oa1 += z * w301;
            z = fmaxf(acc[n][1] + bb1, 0.f); oa0 += z * w310; oa1 += z * w311;
            z = fmaxf(acc[n][2] + bb0, 0.f); ob0 += z * w300; ob1 += z * w301;
            z = fmaxf(acc[n][3] + bb1, 0.f); ob0 += z * w310; ob1 += z * w311;
        }
#pragma unroll
        for (int off = 1; off <= 2; off <<= 1) {
            oa0 += __shfl_xor_sync(0xffffffffu, oa0, off);
            oa1 += __shfl_xor_sync(0xffffffffu, oa1, off);
            ob0 += __shfl_xor_sync(0xffffffffu, ob0, off);
            ob1 += __shfl_xor_sync(0xffffffffu, ob1, off);
        }
        if ((lane & 3) == 0) {
            *(float2*)(out + eA * 2) = make_float2(oa0 + b30, oa1 + b31);
            *(float2*)(out + eB * 2) = make_float2(ob0 + b30, ob1 + b31);
        }
        __syncthreads();   // panels reused next tile
    }
}

// ---------------- host orchestration ----------------------------------------
extern "C" void kernel_launch(void* const* d_in, const int* in_sizes, int n_in,
                              void* d_out, int out_size)
{
    (void)in_sizes; (void)n_in; (void)out_size;
    const float* x   = (const float*)d_in[0];
    const void*  ei  = d_in[1];
    const float* ea  = (const float*)d_in[2];
    const float* W1l = (const float*)d_in[3];
    const float* b1l = (const float*)d_in[4];
    const float* W1r = (const float*)d_in[5];
    const float* g1  = (const float*)d_in[6];
    const float* be1 = (const float*)d_in[7];
    const float* W2l = (const float*)d_in[8];
    const float* b2l = (const float*)d_in[9];
    const float* W2r = (const float*)d_in[10];
    const float* g2  = (const float*)d_in[11];
    const float* be2 = (const float*)d_in[12];
    const float* Wm1 = (const float*)d_in[13];
    const float* bm1 = (const float*)d_in[14];
    const float* Wm2 = (const float*)d_in[15];
    const float* bm2 = (const float*)d_in[16];
    const float* Wm3 = (const float*)d_in[17];
    const float* bm3 = (const float*)d_in[18];
    float* out = (float*)d_out;

    float *pY, *pR, *pH, *pStats, *pAb, *pP, *pQ;
    int *pDeg, *pOff, *pFill, *pCsr;
    cudaGetSymbolAddress((void**)&pY, g_y);
    cudaGetSymbolAddress((void**)&pR, g_r);
    cudaGetSymbolAddress((void**)&pH, g_h);
    cudaGetSymbolAddress((void**)&pStats, g_stats);
    cudaGetSymbolAddress((void**)&pAb, g_ab);
    cudaGetSymbolAddress((void**)&pP, g_P);
    cudaGetSymbolAddress((void**)&pQ, g_Q);
    cudaGetSymbolAddress((void**)&pDeg, g_deg);
    cudaGetSymbolAddress((void**)&pOff, g_off);
    cudaGetSymbolAddress((void**)&pFill, g_fill);
    cudaGetSymbolAddress((void**)&pCsr, g_csr);

    const int smemG128 = 128 * 136 * 2 * 2;   // 69632 (W panels only)
    const int smemG64  = 128 * 72 * 2 * 2;    // 36864
    const int smemEdge = 115456;
    cudaFuncSetAttribute(node_gemm_mma<128>, cudaFuncAttributeMaxDynamicSharedMemorySize, smemG128);
    cudaFuncSetAttribute(node_gemm_mma<64>,  cudaFuncAttributeMaxDynamicSharedMemorySize, smemG64);
    cudaFuncSetAttribute(edge_mlp_mma_kernel, cudaFuncAttributeMaxDynamicSharedMemorySize, smemEdge);

    const int NROW_TILES = (NN + 127) / 128;   // 391

    // ---- prologue (gemm128 stays in the profiled 4th-kernel slot) ----
    init_kernel<<<(NN + 255) / 256, 256>>>(ei, pDeg, pFill, pStats); // k1
    hist_kernel<<<(EE + 255) / 256, 256>>>(ei, pDeg);                // k2
    scan_kernel<<<1, 1024>>>(pDeg, pOff);                            // k3
    node_gemm_mma<128><<<dim3(NROW_TILES, 1), 256, smemG128>>>(      // k4 (prof)
        x, W1l, 128, W1r, 128, 64, pY, 64, nullptr, pR, 64, nullptr);
    csr_fill_kernel<<<(EE + 255) / 256, 256>>>(ei, pOff, pFill, pCsr);

    // ---- layer 1 aggregate + BN ----
    aggregate_kernel<<<NN / 8, 256>>>(pOff, pCsr, pY, pR, b1l, pH, pStats);
    bn_param_kernel<<<1, 64>>>(pStats, g1, be1, pAb);   // also re-zeroes stats

    // ---- layer 2 ----
    node_gemm_mma<64><<<dim3(NROW_TILES, 1), 256, smemG64>>>(
        pH, W2l, 64, W2r, 64, 64, pY, 64, nullptr, pR, 64, pAb);
    aggregate_kernel<<<NN / 8, 256>>>(pOff, pCsr, pY, pR, b2l, pH, pStats);
    bn_param_kernel<<<1, 64>>>(pStats, g2, be2, pAb + 128);

    // ---- node precompute for edge MLP: P (with bm1) and Q ----
    node_gemm_mma<64><<<dim3(NROW_TILES, 2), 256, smemG64>>>(
        pH, Wm1, 144, Wm1 + 80, 144, 128, pP, 128, bm1, pQ, 128, pAb + 128);

    // ---- per-edge MLP fully on mma.sync tensor cores (persistent) ----
    edge_mlp_mma_kernel<<<PERSIST_BLOCKS, 256, smemEdge>>>(
        ei, ea, pP, pQ, Wm1, Wm2, bm2, Wm3, bm3, out);
}

// round 17
// speedup vs baseline: 1.2256x; 1.0847x over previous
#include <cuda_runtime.h>
#include <cuda_bf16.h>
#include <cstdint>
#include <math.h>

#define NN 50000
#define EE 800000
#define NTILES (EE / 128)          // 6250 edge tiles
#define PERSIST_BLOCKS 296         // 148 SMs x 2 blocks

// ---------------- scratch (device globals; no allocations allowed) ----------
__device__ float g_y[NN * 64];      // messages y = h @ Wl^T
__device__ float g_r[NN * 64];      // root    r = h @ Wr^T
__device__ float g_h[NN * 64];      // pre-BN hidden
__device__ float g_stats[128];      // per-channel sum / sumsq
__device__ float g_ab[256];         // BN affine: [a1|c1|a2|c2]
__device__ float g_P[NN * 128];     // P = hf @ Wm1[:, :64]^T + bm1
__device__ float g_Q[NN * 128];     // Q = hf @ Wm1[:, 80:]^T
__device__ int   g_deg[NN];         // in-degree
__device__ int   g_off[NN + 1];     // CSR offsets
__device__ int   g_fill[NN];        // fill cursors
__device__ int   g_csr[EE];         // src node per CSR slot (grouped by dst)
__device__ int   g_idx64;           // 1 if edge_index is int64, 0 if int32

// ---------------- portable bf16 HMMA (sm_80+ PTX, works on compute_103) -----
__device__ __forceinline__ void mma16816(float* d,
                                         uint32_t a0, uint32_t a1,
                                         uint32_t a2, uint32_t a3,
                                         uint32_t b0, uint32_t b1) {
    asm volatile(
        "mma.sync.aligned.m16n8k16.row.col.f32.bf16.bf16.f32 "
        "{%0,%1,%2,%3}, {%4,%5,%6,%7}, {%8,%9}, {%0,%1,%2,%3};"
        : "+f"(d[0]), "+f"(d[1]), "+f"(d[2]), "+f"(d[3])
        : "r"(a0), "r"(a1), "r"(a2), "r"(a3), "r"(b0), "r"(b1));
}

__device__ __forceinline__ void ldsm_x4(uint32_t& r0, uint32_t& r1,
                                        uint32_t& r2, uint32_t& r3,
                                        uint32_t addr) {
    asm volatile(
        "ldmatrix.sync.aligned.m8n8.x4.shared.b16 {%0,%1,%2,%3}, [%4];"
        : "=r"(r0), "=r"(r1), "=r"(r2), "=r"(r3) : "r"(addr));
}

__device__ __forceinline__ uint32_t smem_u32(const void* p) {
    return (uint32_t)__cvta_generic_to_shared(p);
}

__device__ __forceinline__ void split_bf16x2(float2 v, uint32_t& h, uint32_t& l) {
    __nv_bfloat16 h0 = __float2bfloat16_rn(v.x);
    __nv_bfloat16 h1 = __float2bfloat16_rn(v.y);
    __nv_bfloat16 l0 = __float2bfloat16_rn(v.x - __bfloat162float(h0));
    __nv_bfloat16 l1 = __float2bfloat16_rn(v.y - __bfloat162float(h1));
    h = ((uint32_t)__bfloat16_as_ushort(h1) << 16) | __bfloat16_as_ushort(h0);
    l = ((uint32_t)__bfloat16_as_ushort(l1) << 16) | __bfloat16_as_ushort(l0);
}

__device__ __forceinline__ void split_bf16x4(float4 v, uint2& hp, uint2& lp) {
    split_bf16x2(make_float2(v.x, v.y), hp.x, lp.x);
    split_bf16x2(make_float2(v.z, v.w), hp.y, lp.y);
}

// ---------------- init: zero deg/fill/stats + dtype detection ----------------
__global__ void init_kernel(const void* ei, int* __restrict__ deg,
                            int* __restrict__ fill, float* __restrict__ stats) {
    int i = blockIdx.x * blockDim.x + threadIdx.x;
    if (i < NN) { deg[i] = 0; fill[i] = 0; }
    if (i < 128) stats[i] = 0.f;
    if (i == 0) {
        const unsigned int* w = (const unsigned int*)ei;
        int f = 1;
        for (int k = 0; k < 32; k++)
            if (w[2 * k + 1] != 0u) f = 0;   // int32 data: odd words random
        g_idx64 = f;
    }
}

__device__ __forceinline__ int load_idx(const void* ei, long long i, int is64) {
    if (is64) return (int)__ldg(((const long long*)ei) + i);
    return __ldg(((const int*)ei) + i);
}

// ---------------- CSR build --------------------------------------------------
__global__ void hist_kernel(const void* __restrict__ ei, int* __restrict__ deg) {
    int e = blockIdx.x * blockDim.x + threadIdx.x;
    if (e >= EE) return;
    int dst = load_idx(ei, (long long)EE + e, g_idx64);
    atomicAdd(deg + dst, 1);
}

__global__ void scan_kernel(const int* __restrict__ deg, int* __restrict__ off) {
    __shared__ int part[1024];
    int tid = threadIdx.x;                 // 1024 threads, 1 block
    const int CH = (NN + 1023) / 1024;     // 49
    int s0 = tid * CH;
    int lsum = 0;
    for (int i = 0; i < CH; i++) {
        int idx = s0 + i;
        if (idx < NN) lsum += deg[idx];
    }
    part[tid] = lsum;
    __syncthreads();
    for (int d = 1; d < 1024; d <<= 1) {
        int v = (tid >= d) ? part[tid - d] : 0;
        __syncthreads();
        part[tid] += v;
        __syncthreads();
    }
    int run = (tid == 0) ? 0 : part[tid - 1];
    for (int i = 0; i < CH; i++) {
        int idx = s0 + i;
        if (idx < NN) { off[idx] = run; run += deg[idx]; }
    }
    if (tid == 1023) off[NN] = run;
}

__global__ void csr_fill_kernel(const void* __restrict__ ei,
                                const int* __restrict__ off,
                                int* __restrict__ fill,
                                int* __restrict__ csr) {
    int e = blockIdx.x * blockDim.x + threadIdx.x;
    if (e >= EE) return;
    int is64 = g_idx64;
    int src = load_idx(ei, e, is64);
    int dst = load_idx(ei, (long long)EE + e, is64);
    int slot = off[dst] + atomicAdd(fill + dst, 1);
    csr[slot] = src;
}

// ---------------- aggregate + finalize + BN stats (half-warp float4) ---------
__global__ void aggregate_kernel(const int* __restrict__ off,
                                 const int* __restrict__ csr,
                                 const float* __restrict__ y,
                                 const float* __restrict__ r,
                                 const float* __restrict__ bl,
                                 float* __restrict__ h,
                                 float* __restrict__ stats) {
    __shared__ float sbuf[128];
    int tid = threadIdx.x;
    int lane = tid & 31, wid = tid >> 5;
    if (tid < 128) sbuf[tid] = 0.f;
    __syncthreads();

    int n = blockIdx.x * 8 + wid;          // 8 warps = 8 nodes per block
    int beg = off[n], end = off[n + 1];
    int half = lane >> 4;                  // 0 or 1
    int c4 = (lane & 15) * 4;              // channel base
    float4 a0 = make_float4(0.f, 0.f, 0.f, 0.f);
    float4 a1 = make_float4(0.f, 0.f, 0.f, 0.f);
    float4 a2 = make_float4(0.f, 0.f, 0.f, 0.f);
    float4 a3 = make_float4(0.f, 0.f, 0.f, 0.f);

    for (int base = beg; base < end; base += 32) {
        int idx = base + lane;
        int s = (idx < end) ? __ldg(csr + idx) : 0;
        int m = min(32, end - base);
        int j = 0;
        for (; j + 8 <= m; j += 8) {
            int s0 = __shfl_sync(0xffffffffu, s, j + half);
            int s1 = __shfl_sync(0xffffffffu, s, j + 2 + half);
            int s2 = __shfl_sync(0xffffffffu, s, j + 4 + half);
            int s3 = __shfl_sync(0xffffffffu, s, j + 6 + half);
            float4 v0 = *(const float4*)(y + (size_t)s0 * 64 + c4);
            float4 v1 = *(const float4*)(y + (size_t)s1 * 64 + c4);
            float4 v2 = *(const float4*)(y + (size_t)s2 * 64 + c4);
            float4 v3 = *(const float4*)(y + (size_t)s3 * 64 + c4);
            a0.x += v0.x; a0.y += v0.y; a0.z += v0.z; a0.w += v0.w;
            a1.x += v1.x; a1.y += v1.y; a1.z += v1.z; a1.w += v1.w;
            a2.x += v2.x; a2.y += v2.y; a2.z += v2.z; a2.w += v2.w;
            a3.x += v3.x; a3.y += v3.y; a3.z += v3.z; a3.w += v3.w;
        }
        for (; j + 2 <= m; j += 2) {
            int sj = __shfl_sync(0xffffffffu, s, j + half);
            float4 v = *(const float4*)(y + (size_t)sj * 64 + c4);
            a0.x += v.x; a0.y += v.y; a0.z += v.z; a0.w += v.w;
        }
        if (j < m) {                       // odd leftover: half 0 only
            int sj = __shfl_sync(0xffffffffu, s, j);
            if (half == 0) {
                float4 v = *(const float4*)(y + (size_t)sj * 64 + c4);
                a0.x += v.x; a0.y += v.y; a0.z += v.z; a0.w += v.w;
            }
        }
    }
    float4 acc;
    acc.x = a0.x + a1.x + a2.x + a3.x;
    acc.y = a0.y + a1.y + a2.y + a3.y;
    acc.z = a0.z + a1.z + a2.z + a3.z;
    acc.w = a0.w + a1.w + a2.w + a3.w;
    acc.x += __shfl_xor_sync(0xffffffffu, acc.x, 16);
    acc.y += __shfl_xor_sync(0xffffffffu, acc.y, 16);
    acc.z += __shfl_xor_sync(0xffffffffu, acc.z, 16);
    acc.w += __shfl_xor_sync(0xffffffffu, acc.w, 16);

    if (half == 0) {
        float inv = 1.f / fmaxf((float)(end - beg), 1.f);
        float4 rv = *(const float4*)(r + (size_t)n * 64 + c4);
        float4 bv = *(const float4*)(bl + c4);
        float4 hv;
        hv.x = acc.x * inv + bv.x + rv.x;
        hv.y = acc.y * inv + bv.y + rv.y;
        hv.z = acc.z * inv + bv.z + rv.z;
        hv.w = acc.w * inv + bv.w + rv.w;
        *(float4*)(h + (size_t)n * 64 + c4) = hv;
        atomicAdd(&sbuf[c4 + 0], hv.x);
        atomicAdd(&sbuf[c4 + 1], hv.y);
        atomicAdd(&sbuf[c4 + 2], hv.z);
        atomicAdd(&sbuf[c4 + 3], hv.w);
        atomicAdd(&sbuf[64 + c4 + 0], hv.x * hv.x);
        atomicAdd(&sbuf[64 + c4 + 1], hv.y * hv.y);
        atomicAdd(&sbuf[64 + c4 + 2], hv.z * hv.z);
        atomicAdd(&sbuf[64 + c4 + 3], hv.w * hv.w);
    }
    __syncthreads();
    if (tid < 128) atomicAdd(stats + tid, sbuf[tid]);
}

// ---------------- BN params (also re-zeroes stats for the next layer) --------
__global__ void bn_param_kernel(float* __restrict__ stats,
                                const float* __restrict__ gamma,
                                const float* __restrict__ beta,
                                float* __restrict__ ab) {
    int c = threadIdx.x;  // 64 threads
    float mu = stats[c] * (1.f / (float)NN);
    float var = stats[64 + c] * (1.f / (float)NN) - mu * mu;
    float a = gamma[c] * rsqrtf(var + 1e-5f);
    ab[c] = a;
    ab[64 + c] = beta[c] - a * mu;
    stats[c] = 0.f;
    stats[64 + c] = 0.f;
}

// ---------------- node GEMM on mma.sync: A from global, B via ldmatrix -------
template <int K>
__global__ void __launch_bounds__(256, 3) node_gemm_mma(
    const float* __restrict__ A,
    const float* __restrict__ B1, int ldb1,
    const float* __restrict__ B2, int ldb2,
    int split,
    float* __restrict__ out1, int w1, const float* __restrict__ bias1,
    float* __restrict__ out2, int w2,
    const float* __restrict__ ab)
{
    constexpr int KP = K + 8;                       // padded row (conflict-free)
    extern __shared__ char smem[];
    const int OF_WHI = 0;                           // 128 * KP * 2
    const int OF_WLO = 128 * KP * 2;

    int tid = threadIdx.x, wid = tid >> 5, lane = tid & 31;
    int colBase = blockIdx.y * 128;
    int n0 = blockIdx.x * 128;

    // ---- stage W hi/lo (float4-wise) ----
    for (int i = tid; i < 128 * K / 4; i += 256) {
        int idx = i * 4;
        int o = idx / K, k = idx % K;
        int colg = colBase + o;
        const float* brow = (colg < split) ? (B1 + (size_t)colg * ldb1)
                                           : (B2 + (size_t)(colg - split) * ldb2);
        float4 w4 = *(const float4*)(brow + k);
        uint2 hp, lp;
        split_bf16x4(w4, hp, lp);
        *(uint2*)(smem + OF_WHI + (o * KP + k) * 2) = hp;
        *(uint2*)(smem + OF_WLO + (o * KP + k) * 2) = lp;
    }
    __syncthreads();

    const int r = lane >> 2;           // 0..7
    const int cq = (lane & 3) * 2;     // 0,2,4,6
    int rA = n0 + wid * 16 + r;
    int rB = rA + 8;
    bool okA = rA < NN, okB = rB < NN;
    const float* rowA = A + (size_t)(okA ? rA : 0) * K;
    const float* rowB = A + (size_t)(okB ? rB : 0) * K;

    // ldmatrix lane base: mat 0 = hi@k0, 1 = hi@k0+8, 2 = lo@k0, 3 = lo@k0+8
    uint32_t sbase = smem_u32(smem);
    int mat = lane >> 3, t = lane & 7;
    uint32_t lbase = sbase + ((mat < 2) ? 0u : (uint32_t)OF_WLO)
                   + (uint32_t)t * (KP * 2) + ((mat & 1) ? 16u : 0u);

#pragma unroll
    for (int half = 0; half < 2; half++) {
        float acc[8][4];
#pragma unroll
        for (int n = 0; n < 8; n++)
#pragma unroll
            for (int j = 0; j < 4; j++) acc[n][j] = 0.f;

#pragma unroll
        for (int ks = 0; ks < K / 16; ks++) {
            int k0 = ks * 16;
            // A-frags straight from global + fused affine/ReLU + split
            float2 f0 = okA ? *(const float2*)(rowA + k0 + cq)
                            : make_float2(0.f, 0.f);
            float2 f2 = okA ? *(const float2*)(rowA + k0 + cq + 8)
                            : make_float2(0.f, 0.f);
            float2 f1 = okB ? *(const float2*)(rowB + k0 + cq)
                            : make_float2(0.f, 0.f);
            float2 f3 = okB ? *(const float2*)(rowB + k0 + cq + 8)
                            : make_float2(0.f, 0.f);
            if (ab) {
                int ka = k0 + cq, kb = k0 + cq + 8;
                float a0 = ab[ka], a1 = ab[ka + 1];
                float c0 = ab[64 + ka], c1 = ab[64 + ka + 1];
                float a8 = ab[kb], a9 = ab[kb + 1];
                float c8 = ab[64 + kb], c9 = ab[64 + kb + 1];
                f0.x = fmaxf(a0 * f0.x + c0, 0.f); f0.y = fmaxf(a1 * f0.y + c1, 0.f);
                f1.x = fmaxf(a0 * f1.x + c0, 0.f); f1.y = fmaxf(a1 * f1.y + c1, 0.f);
                f2.x = fmaxf(a8 * f2.x + c8, 0.f); f2.y = fmaxf(a9 * f2.y + c9, 0.f);
                f3.x = fmaxf(a8 * f3.x + c8, 0.f); f3.y = fmaxf(a9 * f3.y + c9, 0.f);
            }
            uint32_t ah0, ah1, ah2, ah3, al0, al1, al2, al3;
            split_bf16x2(f0, ah0, al0);
            split_bf16x2(f1, ah1, al1);
            split_bf16x2(f2, ah2, al2);
            split_bf16x2(f3, ah3, al3);

#pragma unroll
            for (int n = 0; n < 8; n++) {
                int nn = half * 8 + n;
                uint32_t baddr = lbase + (uint32_t)(nn * 8) * (KP * 2)
                               + (uint32_t)k0 * 2;
                uint32_t bh0, bh1, bl0, bl1;
                ldsm_x4(bh0, bh1, bl0, bl1, baddr);
                mma16816(acc[n], ah0, ah1, ah2, ah3, bh0, bh1);
                mma16816(acc[n], al0, al1, al2, al3, bh0, bh1);
                mma16816(acc[n], ah0, ah1, ah2, ah3, bl0, bl1);
            }
        }

        // ---- epilogue for this half: bias + dual-output split ----
#pragma unroll
        for (int n = 0; n < 8; n++) {
            int nn = half * 8 + n;
            int c0g = colBase + nn * 8 + cq;
            float bia0 = 0.f, bia1 = 0.f;
            if (bias1 != nullptr && c0g < split) {
                bia0 = __ldg(bias1 + c0g);
                bia1 = __ldg(bias1 + c0g + 1);
            }
            float* op;
            int lc, w;
            if (c0g < split) { op = out1; lc = c0g; w = w1; }
            else             { op = out2; lc = c0g - split; w = w2; }
            if (okA)
                *(float2*)(op + (size_t)rA * w + lc) =
                    make_float2(acc[n][0] + bia0, acc[n][1] + bia1);
            if (okB)
                *(float2*)(op + (size_t)rB * w + lc) =
                    make_float2(acc[n][2] + bia0, acc[n][3] + bia1);
        }
    }
}

// ---------------- per-edge MLP: warp-independent tiles -----------------------
// Warp w owns A-panel rows [w*16, w*16+16) exclusively (writes in A2, reads
// in B), so tiles need only __syncwarp() — warps pipeline independently.
// W1e frags use scalar LDS (KE=20 rows are not 16B-aligned for ldmatrix).
#define KPAD 136                      // bf16 elems per row (272 B, conflict-free)
#define KE 20                         // W1e/ea padded row in bf16 (40 B)
__global__ void __launch_bounds__(256, 2) edge_mlp_mma_kernel(
    const void* __restrict__ ei, const float* __restrict__ ea,
    const float* __restrict__ P, const float* __restrict__ Q,
    const float* __restrict__ Wm1, const float* __restrict__ Wm2,
    const float* __restrict__ bm2, const float* __restrict__ Wm3,
    const float* __restrict__ bm3, float* __restrict__ out)
{
    extern __shared__ char smem[];
    const int OF_AHI = 0;                      // 128 * 272 = 34816
    const int OF_ALO = 34816;                  // 34816
    const int OF_BHI = 69632;                  // 64 * 272 = 17408
    const int OF_BLO = 87040;                  // 17408
    const int OF_WEH = 104448;                 // W1e hi: 128 * KE * 2 = 5120
    const int OF_WEL = 109568;                 // W1e lo: 5120
    const int OF_W3  = 114688;                 // 128 fp32 = 512
    const int OF_BM2 = 115200;                 // 64 fp32 = 256
    float* w3s  = (float*)(smem + OF_W3);
    float* bm2s = (float*)(smem + OF_BM2);

    int tid = threadIdx.x, wid = tid >> 5, lane = tid & 31;
    int is64 = g_idx64;

    // ---- stage weights once per block ----
    for (int i = tid; i < 128 * 16; i += 256) {
        int j = i >> 4, k = i & 15;
        float w = __ldg(Wm1 + j * 144 + 64 + k);
        __nv_bfloat16 h = __float2bfloat16_rn(w);
        __nv_bfloat16 l = __float2bfloat16_rn(w - __bfloat162float(h));
        *(unsigned short*)(smem + OF_WEH + (j * KE + k) * 2) = __bfloat16_as_ushort(h);
        *(unsigned short*)(smem + OF_WEL + (j * KE + k) * 2) = __bfloat16_as_ushort(l);
    }
    if (tid < 128) { int c = tid >> 1, t = tid & 1; w3s[tid] = __ldg(Wm3 + t * 64 + c); }
    if (tid < 64) bm2s[tid] = __ldg(bm2 + tid);
    for (int i = tid; i < 64 * 128; i += 256) {
        int o = i >> 7, k = i & 127;
        float w = __ldg(Wm2 + o * 128 + k);
        __nv_bfloat16 h = __float2bfloat16_rn(w);
        __nv_bfloat16 l = __float2bfloat16_rn(w - __bfloat162float(h));
        *(unsigned short*)(smem + OF_BHI + (o * KPAD + k) * 2) = __bfloat16_as_ushort(h);
        *(unsigned short*)(smem + OF_BLO + (o * KPAD + k) * 2) = __bfloat16_as_ushort(l);
    }
    __syncthreads();                    // weights visible to all warps

    const int r = lane >> 2;           // 0..7
    const int cq = (lane & 3) * 2;     // 0,2,4,6
    float b30 = __ldg(bm3), b31 = __ldg(bm3 + 1);

    // ldmatrix lane bases (16B-aligned: KPAD rows = 272 B = 17*16):
    // B (W2):  mat 0 = hi@k0, 1 = hi@k0+8, 2 = lo@k0, 3 = lo@k0+8
    // A (z1):  mat 0 = rows+0@k0, 1 = rows+8@k0, 2 = rows+0@k0+8, 3 = rows+8@k0+8
    uint32_t sbase = smem_u32(smem);
    int mat = lane >> 3, lt = lane & 7;
    uint32_t bBase = sbase + ((mat < 2) ? (uint32_t)OF_BHI : (uint32_t)OF_BLO)
                   + (uint32_t)lt * (KPAD * 2) + ((mat & 1) ? 16u : 0u);
    uint32_t aRow = (uint32_t)(wid * 16 + ((mat & 1) ? 8 : 0) + lt);
    uint32_t aKoff = (uint32_t)(mat >> 1) * 16u;
    uint32_t aHiBase = sbase + (uint32_t)OF_AHI + aRow * (KPAD * 2) + aKoff;
    uint32_t aLoBase = sbase + (uint32_t)OF_ALO + aRow * (KPAD * 2) + aKoff;

    // ---- persistent loop over edge tiles (warp-independent) ----
    for (int tile = blockIdx.x; tile < NTILES; tile += gridDim.x) {
        long long e0 = (long long)tile * 128;
        long long eA = e0 + wid * 16 + r;      // frag row r
        long long eB = eA + 8;                 // frag row r+8

        // phase A1: ea A-frags hi/lo straight from global
        float2 f0 = *(const float2*)(ea + (size_t)eA * 16 + cq);
        float2 f2 = *(const float2*)(ea + (size_t)eA * 16 + cq + 8);
        float2 f1 = *(const float2*)(ea + (size_t)eB * 16 + cq);
        float2 f3 = *(const float2*)(ea + (size_t)eB * 16 + cq + 8);
        uint32_t ah0, ah1, ah2, ah3, al0, al1, al2, al3;
        split_bf16x2(f0, ah0, al0);
        split_bf16x2(f1, ah1, al1);
        split_bf16x2(f2, ah2, al2);
        split_bf16x2(f3, ah3, al3);

        float acc_ea[16][4];
#pragma unroll
        for (int n = 0; n < 16; n++)
#pragma unroll
            for (int j = 0; j < 4; j++) acc_ea[n][j] = 0.f;

#pragma unroll
        for (int n = 0; n < 16; n++) {
            const char* bh = smem + OF_WEH + ((size_t)(n * 8 + r) * KE + cq) * 2;
            const char* bl = smem + OF_WEL + ((size_t)(n * 8 + r) * KE + cq) * 2;
            uint32_t bh0 = *(const uint32_t*)(bh);
            uint32_t bh1 = *(const uint32_t*)(bh + 16);
            uint32_t bl0 = *(const uint32_t*)(bl);
            uint32_t bl1 = *(const uint32_t*)(bl + 16);
            mma16816(acc_ea[n], ah0, ah1, ah2, ah3, bh0, bh1);
            mma16816(acc_ea[n], al0, al1, al2, al3, bh0, bh1);
            mma16816(acc_ea[n], ah0, ah1, ah2, ah3, bl0, bl1);
        }

        // phase A2: gather P/Q in d-frag layout, combine+ReLU, split, store
        int srcA = load_idx(ei, eA, is64);
        int dstA = load_idx(ei, (long long)EE + eA, is64);
        int srcB = load_idx(ei, eB, is64);
        int dstB = load_idx(ei, (long long)EE + eB, is64);
        const float* PA = P + (size_t)srcA * 128;
        const float* QA = Q + (size_t)dstA * 128;
        const float* PB = P + (size_t)srcB * 128;
        const float* QB = Q + (size_t)dstB * 128;
        int rowA = wid * 16 + r, rowB = rowA + 8;
#pragma unroll
        for (int n = 0; n < 16; n++) {
            int c0 = n * 8 + cq;
            float2 p = *(const float2*)(PA + c0);
            float2 q = *(const float2*)(QA + c0);
            float2 z;
            z.x = fmaxf(acc_ea[n][0] + p.x + q.x, 0.f);
            z.y = fmaxf(acc_ea[n][1] + p.y + q.y, 0.f);
            uint32_t h, l;
            split_bf16x2(z, h, l);
            *(uint32_t*)(smem + OF_AHI + ((size_t)rowA * KPAD + c0) * 2) = h;
            *(uint32_t*)(smem + OF_ALO + ((size_t)rowA * KPAD + c0) * 2) = l;
            p = *(const float2*)(PB + c0);
            q = *(const float2*)(QB + c0);
            z.x = fmaxf(acc_ea[n][2] + p.x + q.x, 0.f);
            z.y = fmaxf(acc_ea[n][3] + p.y + q.y, 0.f);
            split_bf16x2(z, h, l);
            *(uint32_t*)(smem + OF_AHI + ((size_t)rowB * KPAD + c0) * 2) = h;
            *(uint32_t*)(smem + OF_ALO + ((size_t)rowB * KPAD + c0) * 2) = l;
        }
        __syncwarp();                  // cross-lane STS -> LDSM visibility

        // phase B: GEMM2 via ldmatrix, warp w -> its own 16 edges x 64 outs
        float acc[8][4];
#pragma unroll
        for (int n = 0; n < 8; n++)
#pragma unroll
            for (int j = 0; j < 4; j++) acc[n][j] = 0.f;

#pragma unroll
        for (int ks = 0; ks < 8; ks++) {
            uint32_t k2 = (uint32_t)(ks * 32);      // k0 * 2 bytes
            uint32_t zh0, zh1, zh2, zh3, zl0, zl1, zl2, zl3;
            ldsm_x4(zh0, zh1, zh2, zh3, aHiBase + k2);
            ldsm_x4(zl0, zl1, zl2, zl3, aLoBase + k2);
#pragma unroll
            for (int n = 0; n < 8; n++) {
                uint32_t baddr = bBase + (uint32_t)(n * 8) * (KPAD * 2) + k2;
                uint32_t bh0, bh1, bl0, bl1;
                ldsm_x4(bh0, bh1, bl0, bl1, baddr);
                mma16816(acc[n], zh0, zh1, zh2, zh3, bh0, bh1);
                mma16816(acc[n], zl0, zl1, zl2, zl3, bh0, bh1);
                mma16816(acc[n], zh0, zh1, zh2, zh3, bl0, bl1);
            }
        }

        // epilogue: bias+ReLU+layer3; d-frag rows {r, r+8}, cols {c, c+1}
        float oa0 = 0.f, oa1 = 0.f, ob0 = 0.f, ob1 = 0.f;
#pragma unroll
        for (int n = 0; n < 8; n++) {
            int c0 = n * 8 + cq, c1 = c0 + 1;
            float w300 = w3s[2 * c0], w301 = w3s[2 * c0 + 1];
            float w310 = w3s[2 * c1], w311 = w3s[2 * c1 + 1];
            float bb0 = bm2s[c0], bb1 = bm2s[c1];
            float z;
            z = fmaxf(acc[n][0] + bb0, 0.f); oa0 += z * w300; oa1 += z * w301;
            z = fmaxf(acc[n][1] + bb1, 0.f); oa0 += z * w310; oa1 += z * w311;
            z = fmaxf(acc[n][2] + bb0, 0.f); ob0 += z * w300; ob1 += z * w301;
            z = fmaxf(acc[n][3] + bb1, 0.f); ob0 += z * w310; ob1 += z * w311;
        }
#pragma unroll
        for (int off = 1; off <= 2; off <<= 1) {
            oa0 += __shfl_xor_sync(0xffffffffu, oa0, off);
            oa1 += __shfl_xor_sync(0xffffffffu, oa1, off);
            ob0 += __shfl_xor_sync(0xffffffffu, ob0, off);
            ob1 += __shfl_xor_sync(0xffffffffu, ob1, off);
        }
        if ((lane & 3) == 0) {
            *(float2*)(out + eA * 2) = make_float2(oa0 + b30, oa1 + b31);
            *(float2*)(out + eB * 2) = make_float2(ob0 + b30, ob1 + b31);
        }
        __syncwarp();                  // LDSM done before next tile's STS
    }
}

// ---------------- host orchestration ----------------------------------------
extern "C" void kernel_launch(void* const* d_in, const int* in_sizes, int n_in,
                              void* d_out, int out_size)
{
    (void)in_sizes; (void)n_in; (void)out_size;
    const float* x   = (const float*)d_in[0];
    const void*  ei  = d_in[1];
    const float* ea  = (const float*)d_in[2];
    const float* W1l = (const float*)d_in[3];
    const float* b1l = (const float*)d_in[4];
    const float* W1r = (const float*)d_in[5];
    const float* g1  = (const float*)d_in[6];
    const float* be1 = (const float*)d_in[7];
    const float* W2l = (const float*)d_in[8];
    const float* b2l = (const float*)d_in[9];
    const float* W2r = (const float*)d_in[10];
    const float* g2  = (const float*)d_in[11];
    const float* be2 = (const float*)d_in[12];
    const float* Wm1 = (const float*)d_in[13];
    const float* bm1 = (const float*)d_in[14];
    const float* Wm2 = (const float*)d_in[15];
    const float* bm2 = (const float*)d_in[16];
    const float* Wm3 = (const float*)d_in[17];
    const float* bm3 = (const float*)d_in[18];
    float* out = (float*)d_out;

    float *pY, *pR, *pH, *pStats, *pAb, *pP, *pQ;
    int *pDeg, *pOff, *pFill, *pCsr;
    cudaGetSymbolAddress((void**)&pY, g_y);
    cudaGetSymbolAddress((void**)&pR, g_r);
    cudaGetSymbolAddress((void**)&pH, g_h);
    cudaGetSymbolAddress((void**)&pStats, g_stats);
    cudaGetSymbolAddress((void**)&pAb, g_ab);
    cudaGetSymbolAddress((void**)&pP, g_P);
    cudaGetSymbolAddress((void**)&pQ, g_Q);
    cudaGetSymbolAddress((void**)&pDeg, g_deg);
    cudaGetSymbolAddress((void**)&pOff, g_off);
    cudaGetSymbolAddress((void**)&pFill, g_fill);
    cudaGetSymbolAddress((void**)&pCsr, g_csr);

    const int smemG128 = 128 * 136 * 2 * 2;   // 69632 (W panels only)
    const int smemG64  = 128 * 72 * 2 * 2;    // 36864
    const int smemEdge = 115456;
    cudaFuncSetAttribute(node_gemm_mma<128>, cudaFuncAttributeMaxDynamicSharedMemorySize, smemG128);
    cudaFuncSetAttribute(node_gemm_mma<64>,  cudaFuncAttributeMaxDynamicSharedMemorySize, smemG64);
    cudaFuncSetAttribute(edge_mlp_mma_kernel, cudaFuncAttributeMaxDynamicSharedMemorySize, smemEdge);

    const int NROW_TILES = (NN + 127) / 128;   // 391

    // ---- prologue (gemm128 stays in the profiled 4th-kernel slot) ----
    init_kernel<<<(NN + 255) / 256, 256>>>(ei, pDeg, pFill, pStats); // k1
    hist_kernel<<<(EE + 255) / 256, 256>>>(ei, pDeg);                // k2
    scan_kernel<<<1, 1024>>>(pDeg, pOff);                            // k3
    node_gemm_mma<128><<<dim3(NROW_TILES, 1), 256, smemG128>>>(      // k4 (prof)
        x, W1l, 128, W1r, 128, 64, pY, 64, nullptr, pR, 64, nullptr);
    csr_fill_kernel<<<(EE + 255) / 256, 256>>>(ei, pOff, pFill, pCsr);

    // ---- layer 1 aggregate + BN ----
    aggregate_kernel<<<NN / 8, 256>>>(pOff, pCsr, pY, pR, b1l, pH, pStats);
    bn_param_kernel<<<1, 64>>>(pStats, g1, be1, pAb);   // also re-zeroes stats

    // ---- layer 2 ----
    node_gemm_mma<64><<<dim3(NROW_TILES, 1), 256, smemG64>>>(
        pH, W2l, 64, W2r, 64, 64, pY, 64, nullptr, pR, 64, pAb);
    aggregate_kernel<<<NN / 8, 256>>>(pOff, pCsr, pY, pR, b2l, pH, pStats);
    bn_param_kernel<<<1, 64>>>(pStats, g2, be2, pAb + 128);

    // ---- node precompute for edge MLP: P (with bm1) and Q ----
    node_gemm_mma<64><<<dim3(NROW_TILES, 2), 256, smemG64>>>(
        pH, Wm1, 144, Wm1 + 80, 144, 128, pP, 128, bm1, pQ, 128, pAb + 128);

    // ---- per-edge MLP fully on mma.sync tensor cores (persistent) ----
    edge_mlp_mma_kernel<<<PERSIST_BLOCKS, 256, smemEdge>>>(
        ei, ea, pP, pQ, Wm1, Wm2, bm2, Wm3, bm3, out);
}